// round 1
// baseline (speedup 1.0000x reference)
#include <cuda_runtime.h>
#include <cstddef>

// Problem constants
#define HW   4096
#define CIN  256
#define CQK  32
#define CV   256
#define NB   8
#define MQKV 320   // 32 q + 32 k + 256 v rows stacked

// Scratch (device globals: allocation-free rule)
__device__ float g_wqkv[MQKV * CIN];                       // packed [320,256]
__device__ float g_qkv[(size_t)NB * MQKV * HW];            // [8,320,4096]
__device__ float g_e[(size_t)NB * HW * HW];                // [8,4096,4096] (E then A in-place)
__device__ float g_o[(size_t)NB * CV * HW];                // [8,256,4096]

// ---------------------------------------------------------------------------
// Pack Wq/Wk/Wv into one [320,256] matrix so QKV projection is one GEMM.
// ---------------------------------------------------------------------------
__global__ void pack_w(const float* __restrict__ Wq,
                       const float* __restrict__ Wk,
                       const float* __restrict__ Wv) {
    int i = blockIdx.x * blockDim.x + threadIdx.x;
    if (i < CQK * CIN)            g_wqkv[i] = Wq[i];
    else if (i < 2 * CQK * CIN)   g_wqkv[i] = Wk[i - CQK * CIN];
    else if (i < MQKV * CIN)      g_wqkv[i] = Wv[i - 2 * CQK * CIN];
}

// ---------------------------------------------------------------------------
// Generic batched GEMM: C[n] = alpha * A[n] @ B[n]
// A [M,K] row-major (lda=K), B [K,L] row-major, C [M,L] row-major.
// Block tile 64x64, K-tile 16, 256 threads, 4x4 per thread.
// M % 64 == 0, K % 16 == 0, L % 64 == 0 (holds for all our shapes).
// ---------------------------------------------------------------------------
__global__ __launch_bounds__(256)
void gemm_nn(const float* __restrict__ A, const float* __restrict__ B,
             float* __restrict__ C, int M, int K, int L,
             size_t sA, size_t sB, size_t sC, const float* __restrict__ alphaPtr) {
    int n = blockIdx.z;
    A += (size_t)n * sA;
    B += (size_t)n * sB;
    C += (size_t)n * sC;

    __shared__ float As[64][16];
    __shared__ float Bs[16][64];

    int tid = threadIdx.x;
    int tx = tid & 15;
    int ty = tid >> 4;
    int row0 = blockIdx.y * 64;
    int col0 = blockIdx.x * 64;

    float acc[4][4] = {};

    for (int kt = 0; kt < K; kt += 16) {
        #pragma unroll
        for (int v = 0; v < 4; v++) {
            int idx = tid + v * 256;
            int r = idx >> 4, c = idx & 15;
            As[r][c] = A[(size_t)(row0 + r) * K + kt + c];
        }
        #pragma unroll
        for (int v = 0; v < 4; v++) {
            int idx = tid + v * 256;
            int r = idx >> 6, c = idx & 63;
            Bs[r][c] = B[(size_t)(kt + r) * L + col0 + c];
        }
        __syncthreads();

        #pragma unroll
        for (int k = 0; k < 16; k++) {
            float a[4], b[4];
            #pragma unroll
            for (int i = 0; i < 4; i++) a[i] = As[ty * 4 + i][k];
            #pragma unroll
            for (int j = 0; j < 4; j++) b[j] = Bs[k][tx * 4 + j];
            #pragma unroll
            for (int i = 0; i < 4; i++)
                #pragma unroll
                for (int j = 0; j < 4; j++)
                    acc[i][j] += a[i] * b[j];
        }
        __syncthreads();
    }

    float alpha = alphaPtr ? *alphaPtr : 1.0f;
    #pragma unroll
    for (int i = 0; i < 4; i++) {
        size_t rowOff = (size_t)(row0 + ty * 4 + i) * L + col0 + tx * 4;
        #pragma unroll
        for (int j = 0; j < 4; j++)
            C[rowOff + j] = alpha * acc[i][j];
    }
}

// ---------------------------------------------------------------------------
// E[n,i,j] = sum_{c<32} q[n,c,i] * k[n,c,j]   (both operands "transposed": K=32)
// Block computes 64x64 tile with K loaded fully into SMEM.
// ---------------------------------------------------------------------------
__global__ __launch_bounds__(256)
void gemm_e(float* __restrict__ E) {
    int n = blockIdx.z;
    const float* q = g_qkv + (size_t)n * MQKV * HW;           // rows 0..31
    const float* k = q + (size_t)CQK * HW;                    // rows 32..63
    float* e = E + (size_t)n * HW * HW;

    __shared__ float Qs[CQK][64];
    __shared__ float Ks[CQK][64];

    int tid = threadIdx.x;
    int tx = tid & 15;
    int ty = tid >> 4;
    int i0 = blockIdx.y * 64;
    int j0 = blockIdx.x * 64;

    #pragma unroll
    for (int v = 0; v < 8; v++) {
        int idx = tid + v * 256;
        int r = idx >> 6, c = idx & 63;
        Qs[r][c] = q[(size_t)r * HW + i0 + c];
        Ks[r][c] = k[(size_t)r * HW + j0 + c];
    }
    __syncthreads();

    float acc[4][4] = {};
    #pragma unroll
    for (int c = 0; c < CQK; c++) {
        float a[4], b[4];
        #pragma unroll
        for (int i = 0; i < 4; i++) a[i] = Qs[c][ty * 4 + i];
        #pragma unroll
        for (int j = 0; j < 4; j++) b[j] = Ks[c][tx * 4 + j];
        #pragma unroll
        for (int i = 0; i < 4; i++)
            #pragma unroll
            for (int j = 0; j < 4; j++)
                acc[i][j] += a[i] * b[j];
    }

    #pragma unroll
    for (int i = 0; i < 4; i++) {
        size_t rowOff = (size_t)(i0 + ty * 4 + i) * HW + j0 + tx * 4;
        #pragma unroll
        for (int j = 0; j < 4; j++)
            e[rowOff + j] = acc[i][j];
    }
}

// ---------------------------------------------------------------------------
// Row softmax over j (4096 elements per row), in-place. One block per row.
// 256 threads, 16 values per thread held in registers (single read, single write).
// ---------------------------------------------------------------------------
__global__ __launch_bounds__(256)
void softmax_rows(float* __restrict__ E) {
    size_t rowOff = ((size_t)blockIdx.y * HW + blockIdx.x) * HW;
    float* row = E + rowOff;
    int tid = threadIdx.x;

    float vals[16];
    float m = -1e30f;
    #pragma unroll
    for (int v = 0; v < 16; v++) {
        vals[v] = row[tid + v * 256];
        m = fmaxf(m, vals[v]);
    }

    __shared__ float red[256];
    red[tid] = m;
    __syncthreads();
    #pragma unroll
    for (int s = 128; s > 0; s >>= 1) {
        if (tid < s) red[tid] = fmaxf(red[tid], red[tid + s]);
        __syncthreads();
    }
    m = red[0];
    __syncthreads();

    float sum = 0.0f;
    #pragma unroll
    for (int v = 0; v < 16; v++) {
        vals[v] = __expf(vals[v] - m);
        sum += vals[v];
    }
    red[tid] = sum;
    __syncthreads();
    #pragma unroll
    for (int s = 128; s > 0; s >>= 1) {
        if (tid < s) red[tid] += red[tid + s];
        __syncthreads();
    }
    float inv = 1.0f / red[0];

    #pragma unroll
    for (int v = 0; v < 16; v++)
        row[tid + v * 256] = vals[v] * inv;
}

// ---------------------------------------------------------------------------
// Launch
// ---------------------------------------------------------------------------
extern "C" void kernel_launch(void* const* d_in, const int* in_sizes, int n_in,
                              void* d_out, int out_size) {
    const float* x     = (const float*)d_in[0];   // [8,256,64,64]
    const float* Wq    = (const float*)d_in[1];   // [32,256]
    const float* Wk    = (const float*)d_in[2];   // [32,256]
    const float* Wv    = (const float*)d_in[3];   // [256,256]
    const float* Wo    = (const float*)d_in[4];   // [256,256]
    const float* gamma = (const float*)d_in[5];   // scalar
    float* out = (float*)d_out;                   // [8,256,64,64]

    float* qkv = nullptr; cudaGetSymbolAddress((void**)&qkv, g_qkv);
    float* e   = nullptr; cudaGetSymbolAddress((void**)&e,   g_e);
    float* o   = nullptr; cudaGetSymbolAddress((void**)&o,   g_o);
    float* wqkv= nullptr; cudaGetSymbolAddress((void**)&wqkv,g_wqkv);

    // 1. pack weights [320,256]
    pack_w<<<(MQKV * CIN + 255) / 256, 256>>>(Wq, Wk, Wv);

    // 2. QKV projection: [320,256] @ [256,4096] per batch
    gemm_nn<<<dim3(HW / 64, MQKV / 64, NB), 256>>>(
        wqkv, x, qkv, MQKV, CIN, HW,
        (size_t)0, (size_t)CIN * HW, (size_t)MQKV * HW, nullptr);

    // 3. E = Q^T K : [4096,4096] per batch (K=32)
    gemm_e<<<dim3(HW / 64, HW / 64, NB), 256>>>(e);

    // 4. softmax rows (in-place E -> A)
    softmax_rows<<<dim3(HW, NB), 256>>>(e);

    // 5. O = V @ A : [256,4096] @ [4096,4096] per batch
    gemm_nn<<<dim3(HW / 64, CV / 64, NB), 256>>>(
        qkv + (size_t)2 * CQK * HW, e, o, CV, HW, HW,
        (size_t)MQKV * HW, (size_t)HW * HW, (size_t)CV * HW, nullptr);

    // 6. out = gamma * Wo @ O : [256,256] @ [256,4096] per batch
    gemm_nn<<<dim3(HW / 64, CIN / 64, NB), 256>>>(
        Wo, o, out, CIN, CV, HW,
        (size_t)0, (size_t)CV * HW, (size_t)CIN * HW, gamma);
}

// round 3
// speedup vs baseline: 2.5280x; 2.5280x over previous
#include <cuda_runtime.h>
#include <cuda_bf16.h>
#include <cstdint>
#include <cstddef>

#define HW   4096
#define CIN  256
#define CQK  32
#define CV   256
#define NB   8
#define MQKV 320
#define JSEG 16

// ---------------- scratch (device globals; allocation-free rule) -----------
__device__ float g_wqkv[MQKV * CIN];
__device__ float g_qkv[(size_t)NB * MQKV * HW];
__device__ float g_e[(size_t)NB * HW * HW];            // Et[j,i]
__device__ float g_mp[(size_t)NB * JSEG * HW];
__device__ float g_sp[(size_t)NB * JSEG * HW];
__device__ float g_m[(size_t)NB * HW];
__device__ float g_s[(size_t)NB * HW];
__device__ __nv_bfloat16 g_phi[(size_t)NB * HW * HW];  // P hi (unnormalized exp)
__device__ __nv_bfloat16 g_plo[(size_t)NB * HW * HW];  // P lo
__device__ __nv_bfloat16 g_vhi[(size_t)NB * CV * HW];  // (V/s) hi
__device__ __nv_bfloat16 g_vlo[(size_t)NB * CV * HW];  // (V/s) lo
__device__ float g_o[(size_t)NB * CV * HW];

// ---------------- mma.sync helpers (base sm_103-legal) ----------------------
static __device__ __forceinline__ uint32_t smem_u32(const void* p) {
    uint32_t a;
    asm("{ .reg .u64 t; cvta.to.shared.u64 t, %1; cvt.u32.u64 %0, t; }" : "=r"(a) : "l"(p));
    return a;
}
#define SW64(x) ((x) ^ (((x) >> 3) & 0x30))
#define LDSM4(r0, r1, r2, r3, addr) \
    asm volatile("ldmatrix.sync.aligned.m8n8.x4.shared.b16 {%0,%1,%2,%3}, [%4];" \
                 : "=r"(r0), "=r"(r1), "=r"(r2), "=r"(r3) : "r"(addr))
#define LDSM2(r0, r1, addr) \
    asm volatile("ldmatrix.sync.aligned.m8n8.x2.shared.b16 {%0,%1}, [%2];" \
                 : "=r"(r0), "=r"(r1) : "r"(addr))
#define MMA16816(c, a, b) \
    asm volatile("mma.sync.aligned.m16n8k16.row.col.f32.bf16.bf16.f32 " \
                 "{%0,%1,%2,%3}, {%4,%5,%6,%7}, {%8,%9}, {%0,%1,%2,%3};" \
                 : "+f"((c)[0]), "+f"((c)[1]), "+f"((c)[2]), "+f"((c)[3]) \
                 : "r"((a)[0]), "r"((a)[1]), "r"((a)[2]), "r"((a)[3]), \
                   "r"((b)[0]), "r"((b)[1]))

// ---------------- pack Wq/Wk/Wv ---------------------------------------------
__global__ void pack_w(const float* __restrict__ Wq, const float* __restrict__ Wk,
                       const float* __restrict__ Wv) {
    int i = blockIdx.x * blockDim.x + threadIdx.x;
    if (i < CQK * CIN)            g_wqkv[i] = Wq[i];
    else if (i < 2 * CQK * CIN)   g_wqkv[i] = Wk[i - CQK * CIN];
    else if (i < MQKV * CIN)      g_wqkv[i] = Wv[i - 2 * CQK * CIN];
}

// ---------------- generic fp32 SIMT GEMM (QKV proj, Wo) ---------------------
__global__ __launch_bounds__(256)
void gemm_nn(const float* __restrict__ A, const float* __restrict__ B,
             float* __restrict__ C, int M, int K, int L,
             size_t sA, size_t sB, size_t sC, const float* __restrict__ alphaPtr) {
    int n = blockIdx.z;
    A += (size_t)n * sA; B += (size_t)n * sB; C += (size_t)n * sC;
    __shared__ float As[64][16];
    __shared__ float Bs[16][64];
    int tid = threadIdx.x, tx = tid & 15, ty = tid >> 4;
    int row0 = blockIdx.y * 64, col0 = blockIdx.x * 64;
    float acc[4][4] = {};
    for (int kt = 0; kt < K; kt += 16) {
        #pragma unroll
        for (int v = 0; v < 4; v++) {
            int idx = tid + v * 256;
            As[idx >> 4][idx & 15] = A[(size_t)(row0 + (idx >> 4)) * K + kt + (idx & 15)];
        }
        #pragma unroll
        for (int v = 0; v < 4; v++) {
            int idx = tid + v * 256;
            Bs[idx >> 6][idx & 63] = B[(size_t)(kt + (idx >> 6)) * L + col0 + (idx & 63)];
        }
        __syncthreads();
        #pragma unroll
        for (int k = 0; k < 16; k++) {
            float a[4], b[4];
            #pragma unroll
            for (int i = 0; i < 4; i++) a[i] = As[ty * 4 + i][k];
            #pragma unroll
            for (int j = 0; j < 4; j++) b[j] = Bs[k][tx * 4 + j];
            #pragma unroll
            for (int i = 0; i < 4; i++)
                #pragma unroll
                for (int j = 0; j < 4; j++) acc[i][j] += a[i] * b[j];
        }
        __syncthreads();
    }
    float alpha = alphaPtr ? *alphaPtr : 1.0f;
    #pragma unroll
    for (int i = 0; i < 4; i++) {
        size_t ro = (size_t)(row0 + ty * 4 + i) * L + col0 + tx * 4;
        #pragma unroll
        for (int j = 0; j < 4; j++) C[ro + j] = alpha * acc[i][j];
    }
}

// ---------------- Et[j,i] = sum_c k[c,j] * q[c,i] ---------------------------
__global__ __launch_bounds__(256)
void gemm_et() {
    int n = blockIdx.z;
    const float* q = g_qkv + (size_t)n * MQKV * HW;
    const float* k = q + (size_t)CQK * HW;
    float* e = g_e + (size_t)n * HW * HW;
    __shared__ float Ks[CQK][64];
    __shared__ float Qs[CQK][64];
    int tid = threadIdx.x, tx = tid & 15, ty = tid >> 4;
    int i0 = blockIdx.x * 64, j0 = blockIdx.y * 64;
    #pragma unroll
    for (int v = 0; v < 8; v++) {
        int idx = tid + v * 256;
        int r = idx >> 6, c = idx & 63;
        Ks[r][c] = k[(size_t)r * HW + j0 + c];
        Qs[r][c] = q[(size_t)r * HW + i0 + c];
    }
    __syncthreads();
    float acc[4][4] = {};
    #pragma unroll
    for (int ch = 0; ch < CQK; ch++) {
        float a[4], b[4];
        #pragma unroll
        for (int i = 0; i < 4; i++) a[i] = Ks[ch][ty * 4 + i];
        #pragma unroll
        for (int j = 0; j < 4; j++) b[j] = Qs[ch][tx * 4 + j];
        #pragma unroll
        for (int i = 0; i < 4; i++)
            #pragma unroll
            for (int j = 0; j < 4; j++) acc[i][j] += a[i] * b[j];
    }
    #pragma unroll
    for (int i = 0; i < 4; i++) {
        size_t ro = (size_t)(j0 + ty * 4 + i) * HW + i0 + tx * 4;
        #pragma unroll
        for (int j = 0; j < 4; j++) e[ro + j] = acc[i][j];
    }
}

// ---------------- column softmax stats over rows j --------------------------
__global__ __launch_bounds__(256)
void colmax_part() {
    int n = blockIdx.z, seg = blockIdx.y;
    int i = blockIdx.x * 256 + threadIdx.x;
    const float* base = g_e + (size_t)n * HW * HW + i;
    float m = -3.4e38f;
    #pragma unroll 8
    for (int r = 0; r < 256; r++)
        m = fmaxf(m, base[(size_t)(seg * 256 + r) * HW]);
    g_mp[((size_t)n * JSEG + seg) * HW + i] = m;
}
__global__ __launch_bounds__(256)
void colmax_fin() {
    size_t t = (size_t)blockIdx.x * 256 + threadIdx.x;
    size_t n = t / HW, i = t % HW;
    float m = -3.4e38f;
    #pragma unroll
    for (int s = 0; s < JSEG; s++)
        m = fmaxf(m, g_mp[(n * JSEG + s) * HW + i]);
    g_m[t] = m;
}
__global__ __launch_bounds__(256)
void exp_write() {
    int n = blockIdx.z, seg = blockIdx.y;
    int i = blockIdx.x * 256 + threadIdx.x;
    float m = g_m[(size_t)n * HW + i];
    const float* base = g_e + (size_t)n * HW * HW + i;
    __nv_bfloat16* phi = g_phi + (size_t)n * HW * HW + i;
    __nv_bfloat16* plo = g_plo + (size_t)n * HW * HW + i;
    float s = 0.0f;
    #pragma unroll 4
    for (int r = 0; r < 256; r++) {
        size_t off = (size_t)(seg * 256 + r) * HW;
        float p = __expf(base[off] - m);
        s += p;
        __nv_bfloat16 hi = __float2bfloat16(p);
        phi[off] = hi;
        plo[off] = __float2bfloat16(p - __bfloat162float(hi));
    }
    g_sp[((size_t)n * JSEG + seg) * HW + i] = s;
}
__global__ __launch_bounds__(256)
void sum_fin() {
    size_t t = (size_t)blockIdx.x * 256 + threadIdx.x;
    size_t n = t / HW, i = t % HW;
    float s = 0.0f;
    #pragma unroll
    for (int sg = 0; sg < JSEG; sg++)
        s += g_sp[(n * JSEG + sg) * HW + i];
    g_s[t] = s;
}
__global__ __launch_bounds__(256)
void conv_v() {
    size_t idx = (size_t)blockIdx.x * 256 + threadIdx.x;
    size_t n = idx / ((size_t)CV * HW);
    size_t rem = idx % ((size_t)CV * HW);
    size_t r = rem / HW, i = rem % HW;
    float v = g_qkv[((size_t)n * MQKV + 2 * CQK + r) * HW + i];
    float vv = v / g_s[n * HW + i];
    __nv_bfloat16 hi = __float2bfloat16(vv);
    g_vhi[idx] = hi;
    g_vlo[idx] = __float2bfloat16(vv - __bfloat162float(hi));
}

// ---------------- HMMA O = V' @ P^T (split bf16, fp32 accum) ----------------
// Block: 128 (v) x 128 (j). 8 warps: 2 in M x 4 in N, warp tile 64x32.
// K chunks of 32; per k16 step: products hh, h*lo(B), lo(A)*h.
#define BK 32
__global__ __launch_bounds__(256, 2)
void mma_o() {
    __shared__ __align__(16) __nv_bfloat16 sAhi[128 * BK];
    __shared__ __align__(16) __nv_bfloat16 sAlo[128 * BK];
    __shared__ __align__(16) __nv_bfloat16 sBhi[128 * BK];
    __shared__ __align__(16) __nv_bfloat16 sBlo[128 * BK];

    int tid = threadIdx.x, lane = tid & 31, wid = tid >> 5;
    int wm = wid & 1;        // warp row (0..1) -> 64 rows
    int wn = wid >> 1;       // warp col (0..3) -> 32 cols
    int n = blockIdx.z, j0 = blockIdx.x * 128, v0 = blockIdx.y * 128;

    const __nv_bfloat16* Ahi = g_vhi + ((size_t)n * CV + v0) * HW;
    const __nv_bfloat16* Alo = g_vlo + ((size_t)n * CV + v0) * HW;
    const __nv_bfloat16* Bhi = g_phi + (size_t)n * HW * HW + (size_t)j0 * HW;
    const __nv_bfloat16* Blo = g_plo + (size_t)n * HW * HW + (size_t)j0 * HW;

    uint32_t sa_hi = smem_u32(sAhi), sa_lo = smem_u32(sAlo);
    uint32_t sb_hi = smem_u32(sBhi), sb_lo = smem_u32(sBlo);

    float acc[4][4][4] = {};

    for (int ck = 0; ck < HW / BK; ck++) {
        // fill SMEM: 512 16B-chunks per buffer, 2 per thread per buffer
        #pragma unroll
        for (int t = 0; t < 2; t++) {
            int idx = tid + t * 256;          // 0..511
            int row = idx >> 2, ch = idx & 3; // 4 x 16B chunks per 64B row
            uint32_t off = row * 64 + ch * 16;
            uint32_t sw = SW64(off);
            size_t go = (size_t)row * HW + (size_t)ck * BK + ch * 8;
            *(float4*)((char*)sAhi + sw) = *(const float4*)(const void*)(Ahi + go);
            *(float4*)((char*)sAlo + sw) = *(const float4*)(const void*)(Alo + go);
            *(float4*)((char*)sBhi + sw) = *(const float4*)(const void*)(Bhi + go);
            *(float4*)((char*)sBlo + sw) = *(const float4*)(const void*)(Blo + go);
        }
        __syncthreads();

        #pragma unroll
        for (int ks = 0; ks < 2; ks++) {
            uint32_t a[4][4], bh[4][2], bl[4][2];
            // A addresses: row = base + (lane&15), k-half = lane>>4
            uint32_t a_off[4];
            #pragma unroll
            for (int mt = 0; mt < 4; mt++) {
                int r = wm * 64 + mt * 16 + (lane & 15);
                uint32_t off = r * 64 + ks * 32 + (lane >> 4) * 16;
                a_off[mt] = SW64(off);
                LDSM4(a[mt][0], a[mt][1], a[mt][2], a[mt][3], sa_hi + a_off[mt]);
            }
            #pragma unroll
            for (int nt = 0; nt < 4; nt++) {
                int r = wn * 32 + nt * 8 + (lane & 7);
                uint32_t off = r * 64 + ks * 32 + ((lane >> 3) & 1) * 16;
                uint32_t sw = SW64(off);
                LDSM2(bh[nt][0], bh[nt][1], sb_hi + sw);
                LDSM2(bl[nt][0], bl[nt][1], sb_lo + sw);
            }
            // hi*hi and hi*lo
            #pragma unroll
            for (int mt = 0; mt < 4; mt++)
                #pragma unroll
                for (int nt = 0; nt < 4; nt++) {
                    MMA16816(acc[mt][nt], a[mt], bh[nt]);
                    MMA16816(acc[mt][nt], a[mt], bl[nt]);
                }
            // lo*hi (reuse A regs)
            #pragma unroll
            for (int mt = 0; mt < 4; mt++)
                LDSM4(a[mt][0], a[mt][1], a[mt][2], a[mt][3], sa_lo + a_off[mt]);
            #pragma unroll
            for (int mt = 0; mt < 4; mt++)
                #pragma unroll
                for (int nt = 0; nt < 4; nt++)
                    MMA16816(acc[mt][nt], a[mt], bh[nt]);
        }
        __syncthreads();
    }

    // epilogue: c0,c1 -> (row, col), c2,c3 -> (row+8, col)
    #pragma unroll
    for (int mt = 0; mt < 4; mt++) {
        int row = v0 + wm * 64 + mt * 16 + (lane >> 2);
        float* r0 = g_o + ((size_t)n * CV + row) * HW + j0 + wn * 32 + (lane & 3) * 2;
        float* r1 = r0 + 8 * HW;
        #pragma unroll
        for (int nt = 0; nt < 4; nt++) {
            *(float2*)(r0 + nt * 8) = make_float2(acc[mt][nt][0], acc[mt][nt][1]);
            *(float2*)(r1 + nt * 8) = make_float2(acc[mt][nt][2], acc[mt][nt][3]);
        }
    }
}

// ---------------- launch ----------------------------------------------------
extern "C" void kernel_launch(void* const* d_in, const int* in_sizes, int n_in,
                              void* d_out, int out_size) {
    const float* x     = (const float*)d_in[0];
    const float* Wq    = (const float*)d_in[1];
    const float* Wk    = (const float*)d_in[2];
    const float* Wv    = (const float*)d_in[3];
    const float* Wo    = (const float*)d_in[4];
    const float* gamma = (const float*)d_in[5];
    float* out = (float*)d_out;

    float* qkv  = nullptr; cudaGetSymbolAddress((void**)&qkv,  g_qkv);
    float* o    = nullptr; cudaGetSymbolAddress((void**)&o,    g_o);
    float* wqkv = nullptr; cudaGetSymbolAddress((void**)&wqkv, g_wqkv);

    // 1. pack weights
    pack_w<<<(MQKV * CIN + 255) / 256, 256>>>(Wq, Wk, Wv);
    // 2. QKV projection
    gemm_nn<<<dim3(HW / 64, MQKV / 64, NB), 256>>>(
        wqkv, x, qkv, MQKV, CIN, HW,
        (size_t)0, (size_t)CIN * HW, (size_t)MQKV * HW, nullptr);
    // 3. Et = K^T Q
    gemm_et<<<dim3(HW / 64, HW / 64, NB), 256>>>();
    // 4. column softmax stats, unnormalized P in split bf16
    colmax_part<<<dim3(HW / 256, JSEG, NB), 256>>>();
    colmax_fin<<<(NB * HW) / 256, 256>>>();
    exp_write<<<dim3(HW / 256, JSEG, NB), 256>>>();
    sum_fin<<<(NB * HW) / 256, 256>>>();
    // 5. V' = V / s in split bf16
    conv_v<<<(NB * CV * HW) / 256, 256>>>();
    // 6. O = V' @ P^T on tensor cores (mma.sync)
    mma_o<<<dim3(HW / 128, CV / 128, NB), 256>>>();
    // 7. out = gamma * Wo @ O
    gemm_nn<<<dim3(HW / 64, CIN / 64, NB), 256>>>(
        Wo, o, out, CIN, CV, HW,
        (size_t)0, (size_t)CV * HW, (size_t)CIN * HW, gamma);
}

// round 4
// speedup vs baseline: 4.0382x; 1.5974x over previous
#include <cuda_runtime.h>
#include <cuda_bf16.h>
#include <cstdint>
#include <cstddef>

#define HW   4096
#define CIN  256
#define CQK  32
#define CV   256
#define NB   8
#define MQKV 320
#define JSEG 16

typedef __nv_bfloat16 bf16;

// ---------------- scratch -----------------------------------------------
__device__ bf16  g_wh[MQKV * CIN];                     // wqkv split hi
__device__ bf16  g_wl[MQKV * CIN];
__device__ bf16  g_woh[CIN * CV];                      // Wo split hi
__device__ bf16  g_wol[CIN * CV];
__device__ bf16  g_xth[(size_t)NB * HW * CIN];         // x^T [l, c]
__device__ bf16  g_xtl[(size_t)NB * HW * CIN];
__device__ float g_qkv[(size_t)NB * MQKV * HW];        // fp32 q,k,v [m, l]
__device__ bf16  g_qkTh[(size_t)NB * HW * 64];         // [l][0:32]=qT, [32:64]=kT
__device__ bf16  g_qkTl[(size_t)NB * HW * 64];
__device__ float g_e[(size_t)NB * HW * HW];            // Et[j,i]
__device__ unsigned int g_menc[(size_t)NB * HW];       // encoded col max
__device__ float g_sp[(size_t)NB * JSEG * HW];
__device__ float g_s[(size_t)NB * HW];
__device__ bf16  g_phi[(size_t)NB * HW * HW];          // P hi only
__device__ bf16  g_vhi[(size_t)NB * CV * HW];
__device__ bf16  g_vlo[(size_t)NB * CV * HW];
__device__ float g_o[(size_t)NB * CV * HW];            // O fp32 [v, l]
__device__ bf16  g_oth[(size_t)NB * HW * CV];          // O^T [l, v]
__device__ bf16  g_otl[(size_t)NB * HW * CV];

// ---------------- helpers -------------------------------------------------
static __device__ __forceinline__ uint32_t smem_u32(const void* p) {
    uint32_t a;
    asm("{ .reg .u64 t; cvta.to.shared.u64 t, %1; cvt.u32.u64 %0, t; }" : "=r"(a) : "l"(p));
    return a;
}
#define SW64(x) ((x) ^ (((x) >> 3) & 0x30))
#define LDSM4(r0, r1, r2, r3, addr) \
    asm volatile("ldmatrix.sync.aligned.m8n8.x4.shared.b16 {%0,%1,%2,%3}, [%4];" \
                 : "=r"(r0), "=r"(r1), "=r"(r2), "=r"(r3) : "r"(addr))
#define LDSM2(r0, r1, addr) \
    asm volatile("ldmatrix.sync.aligned.m8n8.x2.shared.b16 {%0,%1}, [%2];" \
                 : "=r"(r0), "=r"(r1) : "r"(addr))
#define MMA16816(c, a, b) \
    asm volatile("mma.sync.aligned.m16n8k16.row.col.f32.bf16.bf16.f32 " \
                 "{%0,%1,%2,%3}, {%4,%5,%6,%7}, {%8,%9}, {%0,%1,%2,%3};" \
                 : "+f"((c)[0]), "+f"((c)[1]), "+f"((c)[2]), "+f"((c)[3]) \
                 : "r"((a)[0]), "r"((a)[1]), "r"((a)[2]), "r"((a)[3]), \
                   "r"((b)[0]), "r"((b)[1]))

static __device__ __forceinline__ unsigned int enc_f(float f) {
    unsigned int u = __float_as_uint(f);
    return (u & 0x80000000u) ? ~u : (u | 0x80000000u);
}
static __device__ __forceinline__ float dec_f(unsigned int u) {
    return (u & 0x80000000u) ? __uint_as_float(u ^ 0x80000000u) : __uint_as_float(~u);
}

// ---------------- weight split --------------------------------------------
__global__ void split_w(const float* __restrict__ Wq, const float* __restrict__ Wk,
                        const float* __restrict__ Wv, const float* __restrict__ Wo) {
    int i = blockIdx.x * 256 + threadIdx.x;
    if (i < MQKV * CIN) {
        float v = (i < CQK * CIN) ? Wq[i]
                : (i < 2 * CQK * CIN) ? Wk[i - CQK * CIN]
                : Wv[i - 2 * CQK * CIN];
        bf16 h = __float2bfloat16(v);
        g_wh[i] = h;
        g_wl[i] = __float2bfloat16(v - __bfloat162float(h));
    } else {
        int j = i - MQKV * CIN;
        if (j < CIN * CV) {
            float v = Wo[j];
            bf16 h = __float2bfloat16(v);
            g_woh[j] = h;
            g_wol[j] = __float2bfloat16(v - __bfloat162float(h));
        }
    }
}

__global__ void init_menc() {
    size_t t = (size_t)blockIdx.x * 256 + threadIdx.x;
    if (t < (size_t)NB * HW) g_menc[t] = 0u;
}

// ---------------- transpose + bf16 split: src[R,HW] -> dst[HW,R] -----------
__global__ __launch_bounds__(256)
void trsp(const float* __restrict__ src, bf16* __restrict__ dhi, bf16* __restrict__ dlo,
          int R, size_t sStride, size_t dStride) {
    __shared__ float t[32][33];
    int n = blockIdx.z;
    src += (size_t)n * sStride;
    dhi += (size_t)n * dStride;
    dlo += (size_t)n * dStride;
    int c0 = blockIdx.x * 32, r0 = blockIdx.y * 32;
    int tx = threadIdx.x, ty = threadIdx.y;
    #pragma unroll
    for (int it = 0; it < 4; it++)
        t[ty + 8 * it][tx] = src[(size_t)(r0 + ty + 8 * it) * HW + c0 + tx];
    __syncthreads();
    #pragma unroll
    for (int it = 0; it < 4; it++) {
        float v = t[tx][ty + 8 * it];
        bf16 h = __float2bfloat16(v);
        size_t o = (size_t)(c0 + ty + 8 * it) * R + r0 + tx;
        dhi[o] = h;
        dlo[o] = __float2bfloat16(v - __bfloat162float(h));
    }
}

// ---------------- QKV projection HMMA: C[m,l] = Wqkv @ xT^T -----------------
// grid (HW/128, MQKV/64, NB); block 256 = 8 warps (2m x 4n), warp 32x32.
__global__ __launch_bounds__(256, 2)
void qkv_hmma() {
    __shared__ __align__(16) bf16 sAh[64 * 32], sAl[64 * 32];
    __shared__ __align__(16) bf16 sBh[128 * 32], sBl[128 * 32];
    int tid = threadIdx.x, lane = tid & 31, wid = tid >> 5;
    int wm = wid & 1, wn = wid >> 1;
    int n = blockIdx.z, m0 = blockIdx.y * 64, l0 = blockIdx.x * 128;

    const bf16* xth = g_xth + (size_t)n * HW * CIN;
    const bf16* xtl = g_xtl + (size_t)n * HW * CIN;
    uint32_t sa_h = smem_u32(sAh), sa_l = smem_u32(sAl);
    uint32_t sb_h = smem_u32(sBh), sb_l = smem_u32(sBl);

    float acc[2][4][4] = {};

    for (int ck = 0; ck < CIN / 32; ck++) {
        {   // A: 64x32, 256 chunks; B: 128x32, 512 chunks
            int row = tid >> 2, ch = tid & 3;
            uint32_t sw = SW64(row * 64 + ch * 16);
            size_t ga = (size_t)(m0 + row) * CIN + ck * 32 + ch * 8;
            *(float4*)((char*)sAh + sw) = *(const float4*)(const void*)(g_wh + ga);
            *(float4*)((char*)sAl + sw) = *(const float4*)(const void*)(g_wl + ga);
        }
        #pragma unroll
        for (int t = 0; t < 2; t++) {
            int idx = tid + t * 256;
            int row = idx >> 2, ch = idx & 3;
            uint32_t sw = SW64(row * 64 + ch * 16);
            size_t gb = (size_t)(l0 + row) * CIN + ck * 32 + ch * 8;
            *(float4*)((char*)sBh + sw) = *(const float4*)(const void*)(xth + gb);
            *(float4*)((char*)sBl + sw) = *(const float4*)(const void*)(xtl + gb);
        }
        __syncthreads();

        #pragma unroll
        for (int ks = 0; ks < 2; ks++) {
            uint32_t a[2][4], bh[4][2], bl[4][2];
            uint32_t a_off[2];
            #pragma unroll
            for (int mt = 0; mt < 2; mt++) {
                int r = wm * 32 + mt * 16 + (lane & 15);
                a_off[mt] = SW64(r * 64 + ks * 32 + (lane >> 4) * 16);
                LDSM4(a[mt][0], a[mt][1], a[mt][2], a[mt][3], sa_h + a_off[mt]);
            }
            #pragma unroll
            for (int nt = 0; nt < 4; nt++) {
                int r = wn * 32 + nt * 8 + (lane & 7);
                uint32_t sw = SW64(r * 64 + ks * 32 + ((lane >> 3) & 1) * 16);
                LDSM2(bh[nt][0], bh[nt][1], sb_h + sw);
                LDSM2(bl[nt][0], bl[nt][1], sb_l + sw);
            }
            #pragma unroll
            for (int mt = 0; mt < 2; mt++)
                #pragma unroll
                for (int nt = 0; nt < 4; nt++) {
                    MMA16816(acc[mt][nt], a[mt], bh[nt]);
                    MMA16816(acc[mt][nt], a[mt], bl[nt]);
                }
            #pragma unroll
            for (int mt = 0; mt < 2; mt++)
                LDSM4(a[mt][0], a[mt][1], a[mt][2], a[mt][3], sa_l + a_off[mt]);
            #pragma unroll
            for (int mt = 0; mt < 2; mt++)
                #pragma unroll
                for (int nt = 0; nt < 4; nt++)
                    MMA16816(acc[mt][nt], a[mt], bh[nt]);
        }
        __syncthreads();
    }

    #pragma unroll
    for (int mt = 0; mt < 2; mt++) {
        int m = m0 + wm * 32 + mt * 16 + (lane >> 2);
        float* r0p = g_qkv + ((size_t)n * MQKV + m) * HW + l0 + wn * 32 + (lane & 3) * 2;
        float* r1p = r0p + 8 * HW;
        #pragma unroll
        for (int nt = 0; nt < 4; nt++) {
            *(float2*)(r0p + nt * 8) = make_float2(acc[mt][nt][0], acc[mt][nt][1]);
            *(float2*)(r1p + nt * 8) = make_float2(acc[mt][nt][2], acc[mt][nt][3]);
        }
    }
}

// ---------------- Et HMMA: Et[j,i] = kT @ qT^T, fused col-max ---------------
// grid (HW/128 i, HW/128 j, NB); 8 warps (2x4), warp 64x32.
__global__ __launch_bounds__(256, 2)
void et_hmma() {
    __shared__ __align__(16) bf16 sAh[128 * 32], sAl[128 * 32];
    __shared__ __align__(16) bf16 sBh[128 * 32], sBl[128 * 32];
    int tid = threadIdx.x, lane = tid & 31, wid = tid >> 5;
    int wm = wid & 1, wn = wid >> 1;
    int n = blockIdx.z, i0 = blockIdx.x * 128, j0 = blockIdx.y * 128;

    const bf16* th = g_qkTh + (size_t)n * HW * 64;
    const bf16* tl = g_qkTl + (size_t)n * HW * 64;
    uint32_t sa_h = smem_u32(sAh), sa_l = smem_u32(sAl);
    uint32_t sb_h = smem_u32(sBh), sb_l = smem_u32(sBl);

    #pragma unroll
    for (int t = 0; t < 2; t++) {
        int idx = tid + t * 256;
        int row = idx >> 2, ch = idx & 3;
        uint32_t sw = SW64(row * 64 + ch * 16);
        *(float4*)((char*)sAh + sw) = *(const float4*)(const void*)(th + (size_t)(j0 + row) * 64 + 32 + ch * 8);
        *(float4*)((char*)sAl + sw) = *(const float4*)(const void*)(tl + (size_t)(j0 + row) * 64 + 32 + ch * 8);
        *(float4*)((char*)sBh + sw) = *(const float4*)(const void*)(th + (size_t)(i0 + row) * 64 + ch * 8);
        *(float4*)((char*)sBl + sw) = *(const float4*)(const void*)(tl + (size_t)(i0 + row) * 64 + ch * 8);
    }
    __syncthreads();

    float acc[4][4][4] = {};
    #pragma unroll
    for (int ks = 0; ks < 2; ks++) {
        uint32_t a[4][4], bh[4][2], bl[4][2];
        uint32_t a_off[4];
        #pragma unroll
        for (int mt = 0; mt < 4; mt++) {
            int r = wm * 64 + mt * 16 + (lane & 15);
            a_off[mt] = SW64(r * 64 + ks * 32 + (lane >> 4) * 16);
            LDSM4(a[mt][0], a[mt][1], a[mt][2], a[mt][3], sa_h + a_off[mt]);
        }
        #pragma unroll
        for (int nt = 0; nt < 4; nt++) {
            int r = wn * 32 + nt * 8 + (lane & 7);
            uint32_t sw = SW64(r * 64 + ks * 32 + ((lane >> 3) & 1) * 16);
            LDSM2(bh[nt][0], bh[nt][1], sb_h + sw);
            LDSM2(bl[nt][0], bl[nt][1], sb_l + sw);
        }
        #pragma unroll
        for (int mt = 0; mt < 4; mt++)
            #pragma unroll
            for (int nt = 0; nt < 4; nt++) {
                MMA16816(acc[mt][nt], a[mt], bh[nt]);
                MMA16816(acc[mt][nt], a[mt], bl[nt]);
            }
        #pragma unroll
        for (int mt = 0; mt < 4; mt++)
            LDSM4(a[mt][0], a[mt][1], a[mt][2], a[mt][3], sa_l + a_off[mt]);
        #pragma unroll
        for (int mt = 0; mt < 4; mt++)
            #pragma unroll
            for (int nt = 0; nt < 4; nt++)
                MMA16816(acc[mt][nt], a[mt], bh[nt]);
    }

    float* e = g_e + (size_t)n * HW * HW;
    #pragma unroll
    for (int mt = 0; mt < 4; mt++) {
        int j = j0 + wm * 64 + mt * 16 + (lane >> 2);
        float* r0p = e + (size_t)j * HW + i0 + wn * 32 + (lane & 3) * 2;
        float* r1p = r0p + 8 * HW;
        #pragma unroll
        for (int nt = 0; nt < 4; nt++) {
            *(float2*)(r0p + nt * 8) = make_float2(acc[mt][nt][0], acc[mt][nt][1]);
            *(float2*)(r1p + nt * 8) = make_float2(acc[mt][nt][2], acc[mt][nt][3]);
        }
    }
    // fused column max (over j) -> atomicMax per column i
    #pragma unroll
    for (int nt = 0; nt < 4; nt++) {
        #pragma unroll
        for (int c = 0; c < 2; c++) {
            float m = -3.4e38f;
            #pragma unroll
            for (int mt = 0; mt < 4; mt++)
                m = fmaxf(m, fmaxf(acc[mt][nt][c], acc[mt][nt][c + 2]));
            m = fmaxf(m, __shfl_xor_sync(0xFFFFFFFFu, m, 4));
            m = fmaxf(m, __shfl_xor_sync(0xFFFFFFFFu, m, 8));
            m = fmaxf(m, __shfl_xor_sync(0xFFFFFFFFu, m, 16));
            if ((lane >> 2) == 0) {
                int i = i0 + wn * 32 + nt * 8 + (lane & 3) * 2 + c;
                atomicMax(&g_menc[(size_t)n * HW + i], enc_f(m));
            }
        }
    }
}

// ---------------- exp + partial sums ---------------------------------------
__global__ __launch_bounds__(256)
void exp_write() {
    int n = blockIdx.z, seg = blockIdx.y;
    int i = blockIdx.x * 256 + threadIdx.x;
    float m = dec_f(g_menc[(size_t)n * HW + i]);
    const float* base = g_e + (size_t)n * HW * HW + i;
    bf16* phi = g_phi + (size_t)n * HW * HW + i;
    float s = 0.0f;
    #pragma unroll 4
    for (int r = 0; r < 256; r++) {
        size_t off = (size_t)(seg * 256 + r) * HW;
        float p = __expf(base[off] - m);
        s += p;
        phi[off] = __float2bfloat16(p);
    }
    g_sp[((size_t)n * JSEG + seg) * HW + i] = s;
}
__global__ __launch_bounds__(256)
void sum_fin() {
    size_t t = (size_t)blockIdx.x * 256 + threadIdx.x;
    size_t n = t / HW, i = t % HW;
    float s = 0.0f;
    #pragma unroll
    for (int sg = 0; sg < JSEG; sg++)
        s += g_sp[(n * JSEG + sg) * HW + i];
    g_s[t] = s;
}
__global__ __launch_bounds__(256)
void conv_v() {
    size_t idx = (size_t)blockIdx.x * 256 + threadIdx.x;
    size_t n = idx / ((size_t)CV * HW);
    size_t rem = idx % ((size_t)CV * HW);
    size_t r = rem / HW, i = rem % HW;
    float v = g_qkv[((size_t)n * MQKV + 2 * CQK + r) * HW + i];
    float vv = v / g_s[n * HW + i];
    bf16 h = __float2bfloat16(vv);
    g_vhi[idx] = h;
    g_vlo[idx] = __float2bfloat16(vv - __bfloat162float(h));
}

// ---------------- O = V' @ P^T (2 products) ---------------------------------
#define BK 32
__global__ __launch_bounds__(256, 2)
void mma_o() {
    __shared__ __align__(16) bf16 sAh[128 * BK], sAl[128 * BK], sBh[128 * BK];
    int tid = threadIdx.x, lane = tid & 31, wid = tid >> 5;
    int wm = wid & 1, wn = wid >> 1;
    int n = blockIdx.z, j0 = blockIdx.x * 128, v0 = blockIdx.y * 128;

    const bf16* Ahi = g_vhi + ((size_t)n * CV + v0) * HW;
    const bf16* Alo = g_vlo + ((size_t)n * CV + v0) * HW;
    const bf16* Bhi = g_phi + (size_t)n * HW * HW + (size_t)j0 * HW;
    uint32_t sa_h = smem_u32(sAh), sa_l = smem_u32(sAl), sb_h = smem_u32(sBh);

    float acc[4][4][4] = {};

    for (int ck = 0; ck < HW / BK; ck++) {
        #pragma unroll
        for (int t = 0; t < 2; t++) {
            int idx = tid + t * 256;
            int row = idx >> 2, ch = idx & 3;
            uint32_t sw = SW64(row * 64 + ch * 16);
            size_t go = (size_t)row * HW + (size_t)ck * BK + ch * 8;
            *(float4*)((char*)sAh + sw) = *(const float4*)(const void*)(Ahi + go);
            *(float4*)((char*)sAl + sw) = *(const float4*)(const void*)(Alo + go);
            *(float4*)((char*)sBh + sw) = *(const float4*)(const void*)(Bhi + go);
        }
        __syncthreads();

        #pragma unroll
        for (int ks = 0; ks < 2; ks++) {
            uint32_t a[4][4], bh[4][2];
            uint32_t a_off[4];
            #pragma unroll
            for (int mt = 0; mt < 4; mt++) {
                int r = wm * 64 + mt * 16 + (lane & 15);
                a_off[mt] = SW64(r * 64 + ks * 32 + (lane >> 4) * 16);
                LDSM4(a[mt][0], a[mt][1], a[mt][2], a[mt][3], sa_h + a_off[mt]);
            }
            #pragma unroll
            for (int nt = 0; nt < 4; nt++) {
                int r = wn * 32 + nt * 8 + (lane & 7);
                uint32_t sw = SW64(r * 64 + ks * 32 + ((lane >> 3) & 1) * 16);
                LDSM2(bh[nt][0], bh[nt][1], sb_h + sw);
            }
            #pragma unroll
            for (int mt = 0; mt < 4; mt++)
                #pragma unroll
                for (int nt = 0; nt < 4; nt++)
                    MMA16816(acc[mt][nt], a[mt], bh[nt]);
            #pragma unroll
            for (int mt = 0; mt < 4; mt++)
                LDSM4(a[mt][0], a[mt][1], a[mt][2], a[mt][3], sa_l + a_off[mt]);
            #pragma unroll
            for (int mt = 0; mt < 4; mt++)
                #pragma unroll
                for (int nt = 0; nt < 4; nt++)
                    MMA16816(acc[mt][nt], a[mt], bh[nt]);
        }
        __syncthreads();
    }

    #pragma unroll
    for (int mt = 0; mt < 4; mt++) {
        int row = v0 + wm * 64 + mt * 16 + (lane >> 2);
        float* r0p = g_o + ((size_t)n * CV + row) * HW + j0 + wn * 32 + (lane & 3) * 2;
        float* r1p = r0p + 8 * HW;
        #pragma unroll
        for (int nt = 0; nt < 4; nt++) {
            *(float2*)(r0p + nt * 8) = make_float2(acc[mt][nt][0], acc[mt][nt][1]);
            *(float2*)(r1p + nt * 8) = make_float2(acc[mt][nt][2], acc[mt][nt][3]);
        }
    }
}

// ---------------- out = gamma * Wo @ O ---------------------------------------
// grid (HW/128, CIN/128, NB); 8 warps (2x4), warp 64x32; K=256.
__global__ __launch_bounds__(256, 2)
void wo_hmma(float* __restrict__ out, const float* __restrict__ gammaPtr) {
    __shared__ __align__(16) bf16 sAh[128 * 32], sAl[128 * 32];
    __shared__ __align__(16) bf16 sBh[128 * 32], sBl[128 * 32];
    int tid = threadIdx.x, lane = tid & 31, wid = tid >> 5;
    int wm = wid & 1, wn = wid >> 1;
    int n = blockIdx.z, o0 = blockIdx.y * 128, l0 = blockIdx.x * 128;

    const bf16* oth = g_oth + (size_t)n * HW * CV;
    const bf16* otl = g_otl + (size_t)n * HW * CV;
    uint32_t sa_h = smem_u32(sAh), sa_l = smem_u32(sAl);
    uint32_t sb_h = smem_u32(sBh), sb_l = smem_u32(sBl);

    float acc[4][4][4] = {};

    for (int ck = 0; ck < CV / 32; ck++) {
        #pragma unroll
        for (int t = 0; t < 2; t++) {
            int idx = tid + t * 256;
            int row = idx >> 2, ch = idx & 3;
            uint32_t sw = SW64(row * 64 + ch * 16);
            size_t ga = (size_t)(o0 + row) * CV + ck * 32 + ch * 8;
            size_t gb = (size_t)(l0 + row) * CV + ck * 32 + ch * 8;
            *(float4*)((char*)sAh + sw) = *(const float4*)(const void*)(g_woh + ga);
            *(float4*)((char*)sAl + sw) = *(const float4*)(const void*)(g_wol + ga);
            *(float4*)((char*)sBh + sw) = *(const float4*)(const void*)(oth + gb);
            *(float4*)((char*)sBl + sw) = *(const float4*)(const void*)(otl + gb);
        }
        __syncthreads();

        #pragma unroll
        for (int ks = 0; ks < 2; ks++) {
            uint32_t a[4][4], bh[4][2], bl[4][2];
            uint32_t a_off[4];
            #pragma unroll
            for (int mt = 0; mt < 4; mt++) {
                int r = wm * 64 + mt * 16 + (lane & 15);
                a_off[mt] = SW64(r * 64 + ks * 32 + (lane >> 4) * 16);
                LDSM4(a[mt][0], a[mt][1], a[mt][2], a[mt][3], sa_h + a_off[mt]);
            }
            #pragma unroll
            for (int nt = 0; nt < 4; nt++) {
                int r = wn * 32 + nt * 8 + (lane & 7);
                uint32_t sw = SW64(r * 64 + ks * 32 + ((lane >> 3) & 1) * 16);
                LDSM2(bh[nt][0], bh[nt][1], sb_h + sw);
                LDSM2(bl[nt][0], bl[nt][1], sb_l + sw);
            }
            #pragma unroll
            for (int mt = 0; mt < 4; mt++)
                #pragma unroll
                for (int nt = 0; nt < 4; nt++) {
                    MMA16816(acc[mt][nt], a[mt], bh[nt]);
                    MMA16816(acc[mt][nt], a[mt], bl[nt]);
                }
            #pragma unroll
            for (int mt = 0; mt < 4; mt++)
                LDSM4(a[mt][0], a[mt][1], a[mt][2], a[mt][3], sa_l + a_off[mt]);
            #pragma unroll
            for (int mt = 0; mt < 4; mt++)
                #pragma unroll
                for (int nt = 0; nt < 4; nt++)
                    MMA16816(acc[mt][nt], a[mt], bh[nt]);
        }
        __syncthreads();
    }

    float gamma = *gammaPtr;
    #pragma unroll
    for (int mt = 0; mt < 4; mt++) {
        int o = o0 + wm * 64 + mt * 16 + (lane >> 2);
        float* r0p = out + ((size_t)n * CIN + o) * HW + l0 + wn * 32 + (lane & 3) * 2;
        float* r1p = r0p + 8 * HW;
        #pragma unroll
        for (int nt = 0; nt < 4; nt++) {
            *(float2*)(r0p + nt * 8) = make_float2(gamma * acc[mt][nt][0], gamma * acc[mt][nt][1]);
            *(float2*)(r1p + nt * 8) = make_float2(gamma * acc[mt][nt][2], gamma * acc[mt][nt][3]);
        }
    }
}

// ---------------- launch ----------------------------------------------------
extern "C" void kernel_launch(void* const* d_in, const int* in_sizes, int n_in,
                              void* d_out, int out_size) {
    const float* x     = (const float*)d_in[0];
    const float* Wq    = (const float*)d_in[1];
    const float* Wk    = (const float*)d_in[2];
    const float* Wv    = (const float*)d_in[3];
    const float* Wo    = (const float*)d_in[4];
    const float* gamma = (const float*)d_in[5];
    float* out = (float*)d_out;

    float* qkv = nullptr; cudaGetSymbolAddress((void**)&qkv, g_qkv);
    float* o   = nullptr; cudaGetSymbolAddress((void**)&o,   g_o);
    bf16* xth = nullptr;  cudaGetSymbolAddress((void**)&xth, g_xth);
    bf16* xtl = nullptr;  cudaGetSymbolAddress((void**)&xtl, g_xtl);
    bf16* qkh = nullptr;  cudaGetSymbolAddress((void**)&qkh, g_qkTh);
    bf16* qkl = nullptr;  cudaGetSymbolAddress((void**)&qkl, g_qkTl);
    bf16* oth = nullptr;  cudaGetSymbolAddress((void**)&oth, g_oth);
    bf16* otl = nullptr;  cudaGetSymbolAddress((void**)&otl, g_otl);

    // 1. split weights; init col-max
    split_w<<<(MQKV * CIN + CIN * CV + 255) / 256, 256>>>(Wq, Wk, Wv, Wo);
    init_menc<<<(NB * HW + 255) / 256, 256>>>();
    // 2. xT split  [HW, 256]
    trsp<<<dim3(HW / 32, CIN / 32, NB), dim3(32, 8)>>>(
        x, xth, xtl, CIN, (size_t)CIN * HW, (size_t)HW * CIN);
    // 3. QKV projection (HMMA)
    qkv_hmma<<<dim3(HW / 128, MQKV / 64, NB), 256>>>();
    // 4. qT/kT split [HW, 64]
    trsp<<<dim3(HW / 32, 2, NB), dim3(32, 8)>>>(
        qkv, qkh, qkl, 64, (size_t)MQKV * HW, (size_t)HW * 64);
    // 5. Et (HMMA) + fused column max
    et_hmma<<<dim3(HW / 128, HW / 128, NB), 256>>>();
    // 6. exp + partial sums -> P(hi)
    exp_write<<<dim3(HW / 256, JSEG, NB), 256>>>();
    sum_fin<<<(NB * HW) / 256, 256>>>();
    // 7. V' = V / s
    conv_v<<<(NB * CV * HW) / 256, 256>>>();
    // 8. O = V' @ P^T (HMMA, 2 products)
    mma_o<<<dim3(HW / 128, CV / 128, NB), 256>>>();
    // 9. OT split [HW, 256]
    trsp<<<dim3(HW / 32, CV / 32, NB), dim3(32, 8)>>>(
        o, oth, otl, CV, (size_t)CV * HW, (size_t)HW * CV);
    // 10. out = gamma * Wo @ O (HMMA)
    wo_hmma<<<dim3(HW / 128, CIN / 128, NB), 256>>>(out, gamma);
}